// round 4
// baseline (speedup 1.0000x reference)
#include <cuda_runtime.h>
#include <cuda_fp16.h>
#include <math.h>
#include <stdint.h>

#define NMAX 100000
#define EMAX 2000000

// Scratch (alloc-free: __device__ globals)
__device__ float  g_t32[NMAX * 64];    // layer-3 linear output (fp32)
__device__ __half g_t16[NMAX * 64];    // layer-1/2 linear output (fp16)
__device__ float  g_h[NMAX * 64];      // layer activations (fp32)
__device__ int    g_deg[NMAX];
__device__ int    g_incl[NMAX];
__device__ int    g_rp[NMAX + 1];
__device__ int    g_cursor[NMAX];
__device__ int    g_bsum[128];
__device__ int    g_csr[EMAX];

// ---------------------------------------------------------------------------
// Tensor-core GEMM: out[n,64] = in[n,K] @ W[K,64]  via mma.m16n8k8.tf32
// 256 threads (8 warps), 128 rows/block. W pre-staged in fragment layout.
// HALF_OUT: write half2 (layers 1,2) else float2 (layer 3).
// ---------------------------------------------------------------------------
__device__ __forceinline__ uint32_t f2tf32(float f) {
    uint32_t r;
    asm("cvt.rna.tf32.f32 %0, %1;" : "=r"(r) : "f"(f));
    return r;
}

template <int K, bool HALF_OUT>
__global__ __launch_bounds__(256)
void gemm_tc_kernel(const float* __restrict__ in, const float* __restrict__ W,
                    void* __restrict__ out_, int n) {
    constexpr int KS = K / 8;
    __shared__ uint32_t Wf[KS * 8 * 32 * 2];

    const int tid = threadIdx.x;
    for (int idx = tid; idx < K * 64; idx += 256) {
        int k  = idx >> 6;
        int nn = idx & 63;
        int ks = k >> 3, kk = k & 7;
        int ch = kk >> 2, c = kk & 3;
        int nb = nn >> 3, ng = nn & 7;
        int lane = ng * 4 + c;
        Wf[(((ks * 8 + nb) * 32) + lane) * 2 + ch] = f2tf32(W[idx]);
    }
    __syncthreads();

    const int w    = tid >> 5;
    const int lane = tid & 31;
    const int grp  = lane >> 2;
    const int tig  = lane & 3;

    const int r0 = blockIdx.x * 128 + w * 16 + grp;
    const int r1 = r0 + 8;
    const bool v0 = r0 < n;
    const bool v1 = r1 < n;
    const float* p0 = in + (long)r0 * K + tig;
    const float* p1 = in + (long)r1 * K + tig;

    float acc[8][4];
#pragma unroll
    for (int nb = 0; nb < 8; nb++)
#pragma unroll
        for (int j = 0; j < 4; j++) acc[nb][j] = 0.f;

#pragma unroll
    for (int ks = 0; ks < KS; ks++) {
        float a0f = v0 ? __ldg(p0 + ks * 8)     : 0.f;
        float a1f = v1 ? __ldg(p1 + ks * 8)     : 0.f;
        float a2f = v0 ? __ldg(p0 + ks * 8 + 4) : 0.f;
        float a3f = v1 ? __ldg(p1 + ks * 8 + 4) : 0.f;
        uint32_t a0 = f2tf32(a0f), a1 = f2tf32(a1f);
        uint32_t a2 = f2tf32(a2f), a3 = f2tf32(a3f);

        const uint32_t* wbase = &Wf[(ks * 8) * 64 + lane * 2];
#pragma unroll
        for (int nb = 0; nb < 8; nb++) {
            uint2 bb = *(const uint2*)(wbase + nb * 64);
            asm volatile(
                "mma.sync.aligned.m16n8k8.row.col.f32.tf32.tf32.f32 "
                "{%0,%1,%2,%3}, {%4,%5,%6,%7}, {%8,%9}, {%0,%1,%2,%3};"
                : "+f"(acc[nb][0]), "+f"(acc[nb][1]),
                  "+f"(acc[nb][2]), "+f"(acc[nb][3])
                : "r"(a0), "r"(a1), "r"(a2), "r"(a3),
                  "r"(bb.x), "r"(bb.y));
        }
    }

#pragma unroll
    for (int nb = 0; nb < 8; nb++) {
        int col = nb * 8 + tig * 2;
        if (HALF_OUT) {
            __half* out = (__half*)out_;
            if (v0) *(__half2*)&out[(long)r0 * 64 + col] =
                __floats2half2_rn(acc[nb][0], acc[nb][1]);
            if (v1) *(__half2*)&out[(long)r1 * 64 + col] =
                __floats2half2_rn(acc[nb][2], acc[nb][3]);
        } else {
            float* out = (float*)out_;
            if (v0) *(float2*)&out[(long)r0 * 64 + col] = make_float2(acc[nb][0], acc[nb][1]);
            if (v1) *(float2*)&out[(long)r1 * 64 + col] = make_float2(acc[nb][2], acc[nb][3]);
        }
    }
}

// ---------------------------------------------------------------------------
// CSR construction
// ---------------------------------------------------------------------------
__global__ void zero_deg_kernel(int* __restrict__ deg, int n) {
    int i = blockIdx.x * blockDim.x + threadIdx.x;
    if (i < n) deg[i] = 0;
}

__global__ void hist_kernel(const int* __restrict__ ei, int E, int* __restrict__ deg) {
    int e = blockIdx.x * blockDim.x + threadIdx.x;
    if (e < E) atomicAdd(&deg[ei[E + e]], 1);
}

__global__ __launch_bounds__(256)
void scan1_kernel(const int* __restrict__ deg, int n,
                  int* __restrict__ incl, int* __restrict__ bsum) {
    __shared__ int s[1024];
    const int base = blockIdx.x * 1024;
    const int t = threadIdx.x;
#pragma unroll
    for (int j = 0; j < 4; j++) {
        int idx = t + j * 256;
        s[idx] = (base + idx < n) ? deg[base + idx] : 0;
    }
    __syncthreads();
    for (int off = 1; off < 1024; off <<= 1) {
        int v[4];
#pragma unroll
        for (int j = 0; j < 4; j++) {
            int idx = t + j * 256;
            v[j] = (idx >= off) ? s[idx - off] : 0;
        }
        __syncthreads();
#pragma unroll
        for (int j = 0; j < 4; j++) s[t + j * 256] += v[j];
        __syncthreads();
    }
#pragma unroll
    for (int j = 0; j < 4; j++) {
        int idx = t + j * 256;
        if (base + idx < n) incl[base + idx] = s[idx];
    }
    if (t == 0) bsum[blockIdx.x] = s[1023];
}

__global__ __launch_bounds__(128)
void scan2_kernel(int* __restrict__ bsum, int nb) {
    __shared__ int s[128];
    int t = threadIdx.x;
    s[t] = (t < nb) ? bsum[t] : 0;
    __syncthreads();
    for (int off = 1; off < 128; off <<= 1) {
        int v = (t >= off) ? s[t - off] : 0;
        __syncthreads();
        s[t] += v;
        __syncthreads();
    }
    if (t < nb) bsum[t] = s[t];
}

__global__ void scan3_kernel(const int* __restrict__ incl, const int* __restrict__ deg,
                             const int* __restrict__ bsum, int n, int E,
                             int* __restrict__ rp, int* __restrict__ cursor) {
    int i = blockIdx.x * blockDim.x + threadIdx.x;
    if (i >= n) return;
    int b = i >> 10;
    int add = b ? bsum[b - 1] : 0;
    int excl = incl[i] - deg[i] + add;
    rp[i] = excl;
    cursor[i] = excl;
    if (i == n - 1) rp[n] = E;
}

__global__ void fill_kernel(const int* __restrict__ ei, int E,
                            int* __restrict__ cursor, int* __restrict__ csr) {
    int e = blockIdx.x * blockDim.x + threadIdx.x;
    if (e >= E) return;
    int src = ei[e];
    int dst = ei[E + e];
    int pos = atomicAdd(&cursor[dst], 1);
    csr[pos] = src;
}

// ---------------------------------------------------------------------------
// Gather-reduce (fp16 t) + bias + relu. Warp per node; lane owns a half2 pair.
// ---------------------------------------------------------------------------
__global__ __launch_bounds__(256)
void gather_h2_kernel(const int* __restrict__ rp, const int* __restrict__ csr,
                      const __half* __restrict__ t, const float* __restrict__ bias,
                      float* __restrict__ out, int n) {
    int warp = (blockIdx.x * blockDim.x + threadIdx.x) >> 5;
    int lane = threadIdx.x & 31;
    if (warp >= n) return;

    int s0 = rp[warp];
    int s1 = rp[warp + 1];
    const __half2* tp = (const __half2*)t;

    float ax = 0.f, ay = 0.f;
    int e = s0;
    for (; e + 7 < s1; e += 8) {
        float2 v[8];
#pragma unroll
        for (int j = 0; j < 8; j++) {
            int src = __ldg(&csr[e + j]);
            v[j] = __half22float2(tp[(long)src * 32 + lane]);
        }
#pragma unroll
        for (int j = 0; j < 8; j++) { ax += v[j].x; ay += v[j].y; }
    }
    for (; e < s1; e++) {
        int src = __ldg(&csr[e]);
        float2 v = __half22float2(tp[(long)src * 32 + lane]);
        ax += v.x; ay += v.y;
    }

    float2 bb = *(const float2*)&bias[lane * 2];
    float2 r;
    r.x = fmaxf(ax + bb.x, 0.f);
    r.y = fmaxf(ay + bb.y, 0.f);
    *(float2*)&out[(long)warp * 64 + lane * 2] = r;
}

// ---------------------------------------------------------------------------
// Gather-reduce (fp32 t) + bias + sigmoid (final layer).
// ---------------------------------------------------------------------------
__global__ __launch_bounds__(256)
void gather_f32_sig_kernel(const int* __restrict__ rp, const int* __restrict__ csr,
                           const float* __restrict__ t, const float* __restrict__ bias,
                           float* __restrict__ out, int n) {
    int warp = (blockIdx.x * blockDim.x + threadIdx.x) >> 5;
    int lane = threadIdx.x & 31;
    if (warp >= n) return;

    int s0 = rp[warp];
    int s1 = rp[warp + 1];

    float ax = 0.f, ay = 0.f;
    int e = s0;
    for (; e + 3 < s1; e += 4) {
        int src0 = __ldg(&csr[e + 0]);
        int src1 = __ldg(&csr[e + 1]);
        int src2 = __ldg(&csr[e + 2]);
        int src3 = __ldg(&csr[e + 3]);
        float2 v0 = *(const float2*)&t[(long)src0 * 64 + lane * 2];
        float2 v1 = *(const float2*)&t[(long)src1 * 64 + lane * 2];
        float2 v2 = *(const float2*)&t[(long)src2 * 64 + lane * 2];
        float2 v3 = *(const float2*)&t[(long)src3 * 64 + lane * 2];
        ax += (v0.x + v1.x) + (v2.x + v3.x);
        ay += (v0.y + v1.y) + (v2.y + v3.y);
    }
    for (; e < s1; e++) {
        int src = __ldg(&csr[e]);
        float2 v = *(const float2*)&t[(long)src * 64 + lane * 2];
        ax += v.x; ay += v.y;
    }

    float2 bb = *(const float2*)&bias[lane * 2];
    ax += bb.x; ay += bb.y;
    float2 r;
    r.x = 1.f / (1.f + __expf(-ax));
    r.y = 1.f / (1.f + __expf(-ay));
    *(float2*)&out[(long)warp * 64 + lane * 2] = r;
}

extern "C" void kernel_launch(void* const* d_in, const int* in_sizes, int n_in,
                              void* d_out, int out_size) {
    const float* x  = (const float*)d_in[0];
    const int*   ei = (const int*)d_in[1];
    const float* W1 = (const float*)d_in[2];
    const float* b1 = (const float*)d_in[3];
    const float* W2 = (const float*)d_in[4];
    const float* b2 = (const float*)d_in[5];
    const float* W3 = (const float*)d_in[6];
    const float* b3 = (const float*)d_in[7];
    float* out = (float*)d_out;

    const int N = in_sizes[0] / 128;
    const int E = in_sizes[1] / 2;

    float *t32, *h;
    __half* t16;
    int *deg, *incl, *rp, *cursor, *bsum, *csr;
    cudaGetSymbolAddress((void**)&t32,    g_t32);
    cudaGetSymbolAddress((void**)&t16,    g_t16);
    cudaGetSymbolAddress((void**)&h,      g_h);
    cudaGetSymbolAddress((void**)&deg,    g_deg);
    cudaGetSymbolAddress((void**)&incl,   g_incl);
    cudaGetSymbolAddress((void**)&rp,     g_rp);
    cudaGetSymbolAddress((void**)&cursor, g_cursor);
    cudaGetSymbolAddress((void**)&bsum,   g_bsum);
    cudaGetSymbolAddress((void**)&csr,    g_csr);

    const int nb_scan = (N + 1023) / 1024;
    const int nblk = (N + 255) / 256;
    const int eblk = (E + 255) / 256;
    const int gb   = (N + 127) / 128;
    const int wb   = (N + 7) / 8;

    // Fork: CSR build runs on a side stream, concurrent with GEMM-1.
    cudaStream_t s2;
    cudaStreamCreateWithFlags(&s2, cudaStreamNonBlocking);
    cudaEvent_t evFork, evJoin;
    cudaEventCreateWithFlags(&evFork, cudaEventDisableTiming);
    cudaEventCreateWithFlags(&evJoin, cudaEventDisableTiming);

    cudaEventRecord(evFork, 0);
    cudaStreamWaitEvent(s2, evFork, 0);

    // --- CSR build (side stream) ---
    zero_deg_kernel<<<nblk, 256, 0, s2>>>(deg, N);
    hist_kernel<<<eblk, 256, 0, s2>>>(ei, E, deg);
    scan1_kernel<<<nb_scan, 256, 0, s2>>>(deg, N, incl, bsum);
    scan2_kernel<<<1, 128, 0, s2>>>(bsum, nb_scan);
    scan3_kernel<<<nblk, 256, 0, s2>>>(incl, deg, bsum, N, E, rp, cursor);
    fill_kernel<<<eblk, 256, 0, s2>>>(ei, E, cursor, csr);
    cudaEventRecord(evJoin, s2);

    // --- GEMM-1 (main stream, concurrent with CSR) ---
    gemm_tc_kernel<128, true><<<gb, 256>>>(x, W1, t16, N);

    // Join: gather needs both CSR and t16
    cudaStreamWaitEvent(0, evJoin, 0);

    // --- Layer 1 ---
    gather_h2_kernel<<<wb, 256>>>(rp, csr, t16, b1, h, N);

    // --- Layer 2 ---
    gemm_tc_kernel<64, true><<<gb, 256>>>(h, W2, t16, N);
    gather_h2_kernel<<<wb, 256>>>(rp, csr, t16, b2, h, N);

    // --- Layer 3 (fp32 t for output precision) ---
    gemm_tc_kernel<64, false><<<gb, 256>>>(h, W3, t32, N);
    gather_f32_sig_kernel<<<wb, 256>>>(rp, csr, t32, b3, out, N);
}

// round 5
// speedup vs baseline: 1.4089x; 1.4089x over previous
#include <cuda_runtime.h>
#include <cuda_fp16.h>
#include <math.h>
#include <stdint.h>

#define NMAX 100000
#define EMAX 2000000

// Scratch (alloc-free: __device__ globals)
__device__ float  g_t32[NMAX * 64];    // layer-3 linear output (fp32)
__device__ __half g_t16[NMAX * 64];    // layer-1/2 linear output (fp16)
__device__ float  g_h[NMAX * 64];      // layer activations (fp32)
__device__ int    g_deg[NMAX];
__device__ int    g_incl[NMAX];
__device__ int    g_rp[NMAX + 1];
__device__ int    g_cursor[NMAX];
__device__ int    g_bsum[128];
__device__ int    g_csr[EMAX];

// ---------------------------------------------------------------------------
// Tensor-core GEMM: out[n,64] = in[n,K] @ W[K,64]  via mma.m16n8k8.tf32
// 256 threads (8 warps), 128 rows/block. W pre-staged in fragment layout.
// ---------------------------------------------------------------------------
__device__ __forceinline__ uint32_t f2tf32(float f) {
    uint32_t r;
    asm("cvt.rna.tf32.f32 %0, %1;" : "=r"(r) : "f"(f));
    return r;
}

template <int K, bool HALF_OUT>
__global__ __launch_bounds__(256)
void gemm_tc_kernel(const float* __restrict__ in, const float* __restrict__ W,
                    void* __restrict__ out_, int n) {
    constexpr int KS = K / 8;
    __shared__ uint32_t Wf[KS * 8 * 32 * 2];

    const int tid = threadIdx.x;
    for (int idx = tid; idx < K * 64; idx += 256) {
        int k  = idx >> 6;
        int nn = idx & 63;
        int ks = k >> 3, kk = k & 7;
        int ch = kk >> 2, c = kk & 3;
        int nb = nn >> 3, ng = nn & 7;
        int lane = ng * 4 + c;
        Wf[(((ks * 8 + nb) * 32) + lane) * 2 + ch] = f2tf32(W[idx]);
    }
    __syncthreads();

    const int w    = tid >> 5;
    const int lane = tid & 31;
    const int grp  = lane >> 2;
    const int tig  = lane & 3;

    const int r0 = blockIdx.x * 128 + w * 16 + grp;
    const int r1 = r0 + 8;
    const bool v0 = r0 < n;
    const bool v1 = r1 < n;
    const float* p0 = in + (long)r0 * K + tig;
    const float* p1 = in + (long)r1 * K + tig;

    float acc[8][4];
#pragma unroll
    for (int nb = 0; nb < 8; nb++)
#pragma unroll
        for (int j = 0; j < 4; j++) acc[nb][j] = 0.f;

#pragma unroll
    for (int ks = 0; ks < KS; ks++) {
        float a0f = v0 ? __ldg(p0 + ks * 8)     : 0.f;
        float a1f = v1 ? __ldg(p1 + ks * 8)     : 0.f;
        float a2f = v0 ? __ldg(p0 + ks * 8 + 4) : 0.f;
        float a3f = v1 ? __ldg(p1 + ks * 8 + 4) : 0.f;
        uint32_t a0 = f2tf32(a0f), a1 = f2tf32(a1f);
        uint32_t a2 = f2tf32(a2f), a3 = f2tf32(a3f);

        const uint32_t* wbase = &Wf[(ks * 8) * 64 + lane * 2];
#pragma unroll
        for (int nb = 0; nb < 8; nb++) {
            uint2 bb = *(const uint2*)(wbase + nb * 64);
            asm volatile(
                "mma.sync.aligned.m16n8k8.row.col.f32.tf32.tf32.f32 "
                "{%0,%1,%2,%3}, {%4,%5,%6,%7}, {%8,%9}, {%0,%1,%2,%3};"
                : "+f"(acc[nb][0]), "+f"(acc[nb][1]),
                  "+f"(acc[nb][2]), "+f"(acc[nb][3])
                : "r"(a0), "r"(a1), "r"(a2), "r"(a3),
                  "r"(bb.x), "r"(bb.y));
        }
    }

#pragma unroll
    for (int nb = 0; nb < 8; nb++) {
        int col = nb * 8 + tig * 2;
        if (HALF_OUT) {
            __half* out = (__half*)out_;
            if (v0) *(__half2*)&out[(long)r0 * 64 + col] =
                __floats2half2_rn(acc[nb][0], acc[nb][1]);
            if (v1) *(__half2*)&out[(long)r1 * 64 + col] =
                __floats2half2_rn(acc[nb][2], acc[nb][3]);
        } else {
            float* out = (float*)out_;
            if (v0) *(float2*)&out[(long)r0 * 64 + col] = make_float2(acc[nb][0], acc[nb][1]);
            if (v1) *(float2*)&out[(long)r1 * 64 + col] = make_float2(acc[nb][2], acc[nb][3]);
        }
    }
}

// ---------------------------------------------------------------------------
// CSR construction
// ---------------------------------------------------------------------------
__global__ void zero_deg_kernel(int* __restrict__ deg, int n) {
    int i = blockIdx.x * blockDim.x + threadIdx.x;
    if (i < n) deg[i] = 0;
}

__global__ void hist_kernel(const int* __restrict__ ei, int E, int* __restrict__ deg) {
    int e = blockIdx.x * blockDim.x + threadIdx.x;
    if (e < E) atomicAdd(&deg[ei[E + e]], 1);
}

__global__ __launch_bounds__(256)
void scan1_kernel(const int* __restrict__ deg, int n,
                  int* __restrict__ incl, int* __restrict__ bsum) {
    __shared__ int s[1024];
    const int base = blockIdx.x * 1024;
    const int t = threadIdx.x;
#pragma unroll
    for (int j = 0; j < 4; j++) {
        int idx = t + j * 256;
        s[idx] = (base + idx < n) ? deg[base + idx] : 0;
    }
    __syncthreads();
    for (int off = 1; off < 1024; off <<= 1) {
        int v[4];
#pragma unroll
        for (int j = 0; j < 4; j++) {
            int idx = t + j * 256;
            v[j] = (idx >= off) ? s[idx - off] : 0;
        }
        __syncthreads();
#pragma unroll
        for (int j = 0; j < 4; j++) s[t + j * 256] += v[j];
        __syncthreads();
    }
#pragma unroll
    for (int j = 0; j < 4; j++) {
        int idx = t + j * 256;
        if (base + idx < n) incl[base + idx] = s[idx];
    }
    if (t == 0) bsum[blockIdx.x] = s[1023];
}

__global__ __launch_bounds__(128)
void scan2_kernel(int* __restrict__ bsum, int nb) {
    __shared__ int s[128];
    int t = threadIdx.x;
    s[t] = (t < nb) ? bsum[t] : 0;
    __syncthreads();
    for (int off = 1; off < 128; off <<= 1) {
        int v = (t >= off) ? s[t - off] : 0;
        __syncthreads();
        s[t] += v;
        __syncthreads();
    }
    if (t < nb) bsum[t] = s[t];
}

__global__ void scan3_kernel(const int* __restrict__ incl, const int* __restrict__ deg,
                             const int* __restrict__ bsum, int n, int E,
                             int* __restrict__ rp, int* __restrict__ cursor) {
    int i = blockIdx.x * blockDim.x + threadIdx.x;
    if (i >= n) return;
    int b = i >> 10;
    int add = b ? bsum[b - 1] : 0;
    int excl = incl[i] - deg[i] + add;
    rp[i] = excl;
    cursor[i] = excl;
    if (i == n - 1) rp[n] = E;
}

__global__ void fill_kernel(const int* __restrict__ ei, int E,
                            int* __restrict__ cursor, int* __restrict__ csr) {
    int e = blockIdx.x * blockDim.x + threadIdx.x;
    if (e >= E) return;
    int src = ei[e];
    int dst = ei[E + e];
    int pos = atomicAdd(&cursor[dst], 1);
    csr[pos] = src;
}

// ---------------------------------------------------------------------------
// Gather-reduce (fp16 t) + bias + relu. Warp per node; lane owns one half2.
// ---------------------------------------------------------------------------
__global__ __launch_bounds__(256)
void gather_h2_kernel(const int* __restrict__ rp, const int* __restrict__ csr,
                      const __half* __restrict__ t, const float* __restrict__ bias,
                      float* __restrict__ out, int n) {
    int warp = (blockIdx.x * blockDim.x + threadIdx.x) >> 5;
    int lane = threadIdx.x & 31;
    if (warp >= n) return;

    int s0 = rp[warp];
    int s1 = rp[warp + 1];
    const __half2* tp = (const __half2*)t;

    float ax = 0.f, ay = 0.f;
    int e = s0;
    for (; e + 7 < s1; e += 8) {
        float2 v[8];
#pragma unroll
        for (int j = 0; j < 8; j++) {
            int src = __ldg(&csr[e + j]);
            v[j] = __half22float2(tp[(long)src * 32 + lane]);
        }
#pragma unroll
        for (int j = 0; j < 8; j++) { ax += v[j].x; ay += v[j].y; }
    }
    for (; e < s1; e++) {
        int src = __ldg(&csr[e]);
        float2 v = __half22float2(tp[(long)src * 32 + lane]);
        ax += v.x; ay += v.y;
    }

    float2 bb = *(const float2*)&bias[lane * 2];
    float2 r;
    r.x = fmaxf(ax + bb.x, 0.f);
    r.y = fmaxf(ay + bb.y, 0.f);
    *(float2*)&out[(long)warp * 64 + lane * 2] = r;
}

// ---------------------------------------------------------------------------
// Gather-reduce (fp32 t) + bias + sigmoid (final layer).
// ---------------------------------------------------------------------------
__global__ __launch_bounds__(256)
void gather_f32_sig_kernel(const int* __restrict__ rp, const int* __restrict__ csr,
                           const float* __restrict__ t, const float* __restrict__ bias,
                           float* __restrict__ out, int n) {
    int warp = (blockIdx.x * blockDim.x + threadIdx.x) >> 5;
    int lane = threadIdx.x & 31;
    if (warp >= n) return;

    int s0 = rp[warp];
    int s1 = rp[warp + 1];

    float ax = 0.f, ay = 0.f;
    int e = s0;
    for (; e + 3 < s1; e += 4) {
        int src0 = __ldg(&csr[e + 0]);
        int src1 = __ldg(&csr[e + 1]);
        int src2 = __ldg(&csr[e + 2]);
        int src3 = __ldg(&csr[e + 3]);
        float2 v0 = *(const float2*)&t[(long)src0 * 64 + lane * 2];
        float2 v1 = *(const float2*)&t[(long)src1 * 64 + lane * 2];
        float2 v2 = *(const float2*)&t[(long)src2 * 64 + lane * 2];
        float2 v3 = *(const float2*)&t[(long)src3 * 64 + lane * 2];
        ax += (v0.x + v1.x) + (v2.x + v3.x);
        ay += (v0.y + v1.y) + (v2.y + v3.y);
    }
    for (; e < s1; e++) {
        int src = __ldg(&csr[e]);
        float2 v = *(const float2*)&t[(long)src * 64 + lane * 2];
        ax += v.x; ay += v.y;
    }

    float2 bb = *(const float2*)&bias[lane * 2];
    ax += bb.x; ay += bb.y;
    float2 r;
    r.x = 1.f / (1.f + __expf(-ax));
    r.y = 1.f / (1.f + __expf(-ay));
    *(float2*)&out[(long)warp * 64 + lane * 2] = r;
}

extern "C" void kernel_launch(void* const* d_in, const int* in_sizes, int n_in,
                              void* d_out, int out_size) {
    const float* x  = (const float*)d_in[0];
    const int*   ei = (const int*)d_in[1];
    const float* W1 = (const float*)d_in[2];
    const float* b1 = (const float*)d_in[3];
    const float* W2 = (const float*)d_in[4];
    const float* b2 = (const float*)d_in[5];
    const float* W3 = (const float*)d_in[6];
    const float* b3 = (const float*)d_in[7];
    float* out = (float*)d_out;

    const int N = in_sizes[0] / 128;
    const int E = in_sizes[1] / 2;

    float *t32, *h;
    __half* t16;
    int *deg, *incl, *rp, *cursor, *bsum, *csr;
    cudaGetSymbolAddress((void**)&t32,    g_t32);
    cudaGetSymbolAddress((void**)&t16,    g_t16);
    cudaGetSymbolAddress((void**)&h,      g_h);
    cudaGetSymbolAddress((void**)&deg,    g_deg);
    cudaGetSymbolAddress((void**)&incl,   g_incl);
    cudaGetSymbolAddress((void**)&rp,     g_rp);
    cudaGetSymbolAddress((void**)&cursor, g_cursor);
    cudaGetSymbolAddress((void**)&bsum,   g_bsum);
    cudaGetSymbolAddress((void**)&csr,    g_csr);

    const int nb_scan = (N + 1023) / 1024;
    const int nblk = (N + 255) / 256;
    const int eblk = (E + 255) / 256;
    const int gb   = (N + 127) / 128;
    const int wb   = (N + 7) / 8;

    // --- CSR build (single stream, reused by all 3 layers) ---
    zero_deg_kernel<<<nblk, 256>>>(deg, N);
    hist_kernel<<<eblk, 256>>>(ei, E, deg);
    scan1_kernel<<<nb_scan, 256>>>(deg, N, incl, bsum);
    scan2_kernel<<<1, 128>>>(bsum, nb_scan);
    scan3_kernel<<<nblk, 256>>>(incl, deg, bsum, N, E, rp, cursor);
    fill_kernel<<<eblk, 256>>>(ei, E, cursor, csr);

    // --- Layer 1 ---
    gemm_tc_kernel<128, true><<<gb, 256>>>(x, W1, t16, N);
    gather_h2_kernel<<<wb, 256>>>(rp, csr, t16, b1, h, N);

    // --- Layer 2 ---
    gemm_tc_kernel<64, true><<<gb, 256>>>(h, W2, t16, N);
    gather_h2_kernel<<<wb, 256>>>(rp, csr, t16, b2, h, N);

    // --- Layer 3 (fp32 t for output precision) ---
    gemm_tc_kernel<64, false><<<gb, 256>>>(h, W3, t32, N);
    gather_f32_sig_kernel<<<wb, 256>>>(rp, csr, t32, b3, out, N);
}